// round 2
// baseline (speedup 1.0000x reference)
#include <cuda_runtime.h>
#include <math.h>

#define BB   2
#define SEQ  2048
#define HK   16
#define HV   32
#define DK   128
#define DV   128
#define KW   4
#define QKV  8192
#define NTOK (BB*SEQ)
#define EPSF 1e-6f

// ---------------- scratch (device globals: allocation-free) ----------------
__device__ float  g_q[NTOK * HK * DK];   // 33.5 MB  (l2-normalized q)
__device__ float  g_k[NTOK * HK * DK];   // 33.5 MB  (l2-normalized k)
__device__ float  g_v[NTOK * HV * DV];   // 67  MB
__device__ float2 g_gb[NTOK * HV];       // (exp(g), beta) per token/head

// ---------------- kernel 1: depthwise causal conv + SiLU + l2norm ----------
// grid: (NTOK, 64)  block: 128
// slot 0..15  -> q heads (l2norm over 128 ch)
// slot 16..31 -> k heads (l2norm over 128 ch)
// slot 32..63 -> v heads (raw)
__global__ __launch_bounds__(128) void conv_kernel(
    const float* __restrict__ x, const float* __restrict__ w)
{
    const int t    = blockIdx.x;          // global token row (b*SEQ + s)
    const int slot = blockIdx.y;
    const int tid  = threadIdx.x;
    const int ch   = slot * 128 + tid;
    const int s    = t & (SEQ - 1);       // position within sequence

    // conv taps: y[s] = sum_j w[ch,j] * x[s + j - 3]  (zero history per seq)
    const float4 wv = reinterpret_cast<const float4*>(w)[ch];  // w[ch,0..3]
    float acc = wv.w * x[(size_t)t * QKV + ch];
    if (s >= 1) acc += wv.z * x[(size_t)(t - 1) * QKV + ch];
    if (s >= 2) acc += wv.y * x[(size_t)(t - 2) * QKV + ch];
    if (s >= 3) acc += wv.x * x[(size_t)(t - 3) * QKV + ch];

    // SiLU
    float y = acc / (1.0f + __expf(-acc));

    if (slot < 32) {
        // block-wide sum of squares over the 128 channels of this head
        float ss = y * y;
        #pragma unroll
        for (int o = 16; o; o >>= 1) ss += __shfl_xor_sync(0xffffffffu, ss, o);
        __shared__ float red[4];
        if ((tid & 31) == 0) red[tid >> 5] = ss;
        __syncthreads();
        float tot = red[0] + red[1] + red[2] + red[3];
        float r   = rsqrtf(tot + EPSF);
        y *= r;
        if (slot < 16)
            g_q[(size_t)t * HK * DK + slot * DK + tid] = y;
        else
            g_k[(size_t)t * HK * DK + (slot - 16) * DK + tid] = y;
    } else {
        g_v[(size_t)t * HV * DV + (slot - 32) * DV + tid] = y;
    }
}

// ---------------- kernel 2: gating precompute --------------------------------
// g = -exp(alog[h]) * softplus(a + dt_bias[h]);  eg = exp(g); beta = sigmoid(b)
__global__ void gate_kernel(const float* __restrict__ b_in,
                            const float* __restrict__ a_in,
                            const float* __restrict__ dt_bias,
                            const float* __restrict__ alog)
{
    int i = blockIdx.x * blockDim.x + threadIdx.x;
    if (i >= NTOK * HV) return;
    int h = i & (HV - 1);
    float xx = a_in[i] + dt_bias[h];
    // numerically stable softplus: max(x,0) + log1p(exp(-|x|))
    float sp = fmaxf(xx, 0.0f) + log1pf(expf(-fabsf(xx)));
    float g  = -expf(alog[h]) * sp;
    float eg = expf(g);
    float bb = b_in[i];
    float beta = 1.0f / (1.0f + expf(-bb));
    g_gb[i] = make_float2(eg, beta);
}

// ---------------- kernel 3: sequential gated delta-rule scan -----------------
// grid: 64 (= B*HV), block: 128. Thread tid owns state column S[:, tid] in regs.
__global__ __launch_bounds__(128, 1) void scan_kernel(float* __restrict__ out)
{
    const int bh  = blockIdx.x;
    const int bb  = bh / HV;
    const int h   = bh % HV;
    const int hk  = h >> 1;               // GQA: q/k head = h / (HV/HK)
    const int tid = threadIdx.x;           // dv column
    const float scale = 0.08838834764831845f;  // 128^-0.5

    __shared__ float ksh[2][DK];
    __shared__ float qsh[2][DK];

    float Sst[DK];
    #pragma unroll
    for (int i = 0; i < DK; i++) Sst[i] = 0.0f;

    const size_t row0 = (size_t)bb * SEQ;

    // prefetch t = 0
    float kv = g_k[row0 * HK * DK + hk * DK + tid];
    float qv = g_q[row0 * HK * DK + hk * DK + tid];
    float vv = g_v[row0 * HV * DV + h  * DV + tid];
    float2 gb = g_gb[row0 * HV + h];

    for (int t = 0; t < SEQ; t++) {
        const int pb = t & 1;
        ksh[pb][tid] = kv;
        qsh[pb][tid] = qv;
        const float  vcur = vv;
        const float2 gcur = gb;
        __syncthreads();

        // prefetch t+1 (lands while we compute)
        if (t + 1 < SEQ) {
            const size_t r2 = row0 + t + 1;
            kv = g_k[r2 * HK * DK + hk * DK + tid];
            qv = g_q[r2 * HK * DK + hk * DK + tid];
            vv = g_v[r2 * HV * DV + h  * DV + tid];
            gb = g_gb[r2 * HV + h];
        }

        const float eg = gcur.x, beta = gcur.y;
        const float4* k4 = reinterpret_cast<const float4*>(ksh[pb]);
        const float4* q4 = reinterpret_cast<const float4*>(qsh[pb]);

        // loop A: decay state + pred = k^T (eg * S[:,tid])
        float p0 = 0.f, p1 = 0.f, p2 = 0.f, p3 = 0.f;
        #pragma unroll
        for (int i = 0; i < 32; i++) {
            const float4 kk = k4[i];
            Sst[4*i+0] *= eg; Sst[4*i+1] *= eg;
            Sst[4*i+2] *= eg; Sst[4*i+3] *= eg;
            p0 += kk.x * Sst[4*i+0];
            p1 += kk.y * Sst[4*i+1];
            p2 += kk.z * Sst[4*i+2];
            p3 += kk.w * Sst[4*i+3];
        }
        const float pred = (p0 + p1) + (p2 + p3);
        const float u = beta * (vcur - pred);

        // loop B: rank-1 update + output o = scale * q^T S[:,tid]
        float o0 = 0.f, o1 = 0.f, o2 = 0.f, o3 = 0.f;
        #pragma unroll
        for (int i = 0; i < 32; i++) {
            const float4 kk = k4[i];
            const float4 qq = q4[i];
            Sst[4*i+0] += kk.x * u;
            Sst[4*i+1] += kk.y * u;
            Sst[4*i+2] += kk.z * u;
            Sst[4*i+3] += kk.w * u;
            o0 += qq.x * Sst[4*i+0];
            o1 += qq.y * Sst[4*i+1];
            o2 += qq.z * Sst[4*i+2];
            o3 += qq.w * Sst[4*i+3];
        }
        const float o = ((o0 + o1) + (o2 + o3)) * scale;

        // out[(b*SEQ + t) * HV * DV + h * DV + dv]
        out[((row0 + t) * HV + h) * DV + tid] = o;
    }
}

// ---------------- launch ------------------------------------------------------
extern "C" void kernel_launch(void* const* d_in, const int* in_sizes, int n_in,
                              void* d_out, int out_size)
{
    const float* x    = (const float*)d_in[0];  // mixed_qkv [4096, 8192]
    const float* b    = (const float*)d_in[1];  // [4096, 32]
    const float* a    = (const float*)d_in[2];  // [4096, 32]
    const float* w    = (const float*)d_in[3];  // conv_weights [8192, 4]
    const float* dt   = (const float*)d_in[4];  // [32]
    const float* alog = (const float*)d_in[5];  // [32]
    // d_in[6] = cu_seqlens (equal-length; unused)

    conv_kernel<<<dim3(NTOK, 64), 128>>>(x, w);
    gate_kernel<<<(NTOK * HV + 255) / 256, 256>>>(b, a, dt, alog);
    scan_kernel<<<64, 128>>>((float*)d_out);
}